// round 3
// baseline (speedup 1.0000x reference)
#include <cuda_runtime.h>
#include <math.h>

// Problem constants (GCNII_30794915512599)
#define NN   100000      // nodes
#define NE   1600000     // edges
#define FIN  512
#define HID  128
#define NC   64
#define NL   8
#define ALPHA_ 0.1f

// ---------------- scratch (static __device__ — no allocations) ----------------
__device__ int   d_cnt[NN];
__device__ int   d_fill[NN];
__device__ int   d_rowptr[NN + 1];
__device__ float d_dinv[NN];
__device__ int   d_src[NE];
__device__ int   d_dst[NE];
__device__ int   d_csr_src[NE];
__device__ float d_csr_w[NE];
__device__ float d_h [(size_t)NN * HID];
__device__ float d_h0[(size_t)NN * HID];
__device__ float d_s [(size_t)NN * HID];
__device__ int   d_is64;

// ---------------- edge dtype detection ----------------
// edge_index is logically int64 in the reference, but JAX without x64 emits
// int32. Interpreting int32 pairs as uint64 gives values >= 2^32 whenever the
// high word (another node index) is nonzero; true int64 indices are < 100000.
__global__ __launch_bounds__(32) void k_detect(const void* p) {
    const unsigned long long* q = (const unsigned long long*)p;
    bool any_big = false;
    for (int i = threadIdx.x; i < 2048; i += 32)
        if (q[i] > 0xFFFFFFFFull) any_big = true;
    any_big = __any_sync(0xffffffff, any_big);
    if (threadIdx.x == 0) d_is64 = any_big ? 0 : 1;
}

// ---------------- graph preprocessing ----------------
__global__ __launch_bounds__(256) void k_zero() {
    int i = blockIdx.x * blockDim.x + threadIdx.x;
    if (i < NN) { d_cnt[i] = 0; d_fill[i] = 0; }
}

__global__ __launch_bounds__(256) void k_prep_edges(const void* eiv) {
    int e = blockIdx.x * blockDim.x + threadIdx.x;
    if (e >= NE) return;
    int s, d;
    if (d_is64) {
        const long long* ei = (const long long*)eiv;
        s = (int)ei[e];
        d = (int)ei[(size_t)NE + e];
    } else {
        const int* ei = (const int*)eiv;
        s = ei[e];
        d = ei[NE + e];
    }
    // defensive clamp (never faults even if detection were wrong)
    s = min(max(s, 0), NN - 1);
    d = min(max(d, 0), NN - 1);
    d_src[e] = s;
    d_dst[e] = d;
    atomicAdd(&d_cnt[d], 1);
}

__global__ __launch_bounds__(256) void k_dinv() {
    int i = blockIdx.x * blockDim.x + threadIdx.x;
    if (i < NN) d_dinv[i] = rsqrtf((float)(d_cnt[i] + 1));  // +1 self loop
}

// single-block exclusive scan over d_cnt -> d_rowptr
__global__ __launch_bounds__(1024) void k_scan() {
    __shared__ int buf[1024];
    const int t = threadIdx.x;
    const int CH = (NN + 1023) / 1024;   // 98
    const int start = t * CH;
    int s = 0;
    for (int j = 0; j < CH; j++) {
        int idx = start + j;
        if (idx < NN) s += d_cnt[idx];
    }
    buf[t] = s;
    __syncthreads();
    for (int off = 1; off < 1024; off <<= 1) {
        int v = (t >= off) ? buf[t - off] : 0;
        __syncthreads();
        buf[t] += v;
        __syncthreads();
    }
    int run = (t == 0) ? 0 : buf[t - 1];
    for (int j = 0; j < CH; j++) {
        int idx = start + j;
        if (idx < NN) { d_rowptr[idx] = run; run += d_cnt[idx]; }
    }
    if (t == 1023) d_rowptr[NN] = buf[1023];
}

__global__ __launch_bounds__(256) void k_scatter() {
    int e = blockIdx.x * blockDim.x + threadIdx.x;
    if (e >= NE) return;
    int s = d_src[e], d = d_dst[e];
    int pos = d_rowptr[d] + atomicAdd(&d_fill[d], 1);
    d_csr_src[pos] = s;
    d_csr_w[pos]   = d_dinv[s] * d_dinv[d];
}

// ---------------- input GEMM: h = x @ w_in + b_in ; h0 = h ----------------
// BM=64, BN=128, BK=32, 256 threads, thread tile 4x8
__global__ __launch_bounds__(256) void k_gemm_in(const float* __restrict__ X,
                                                 const float* __restrict__ W,
                                                 const float* __restrict__ B) {
    __shared__ float As[32][64];
    __shared__ float Bs[32][128];
    const int tid = threadIdx.x;
    const int blockRow = blockIdx.x * 64;
    const int tx = tid & 15, ty = tid >> 4;
    float acc[4][8];
#pragma unroll
    for (int i = 0; i < 4; i++)
#pragma unroll
        for (int j = 0; j < 8; j++) acc[i][j] = 0.f;

    for (int k0 = 0; k0 < FIN; k0 += 32) {
        // A tile: 64 x 32 (512 float4, 2/thread)
#pragma unroll
        for (int j = 0; j < 2; j++) {
            int idx = tid + j * 256;
            int r = idx >> 3, c4 = idx & 7;
            int grow = blockRow + r;
            float4 v = make_float4(0.f, 0.f, 0.f, 0.f);
            if (grow < NN)
                v = *(const float4*)(X + (size_t)grow * FIN + k0 + c4 * 4);
            As[c4 * 4 + 0][r] = v.x;
            As[c4 * 4 + 1][r] = v.y;
            As[c4 * 4 + 2][r] = v.z;
            As[c4 * 4 + 3][r] = v.w;
        }
        // B tile: 32 x 128 (1024 float4, 4/thread)
#pragma unroll
        for (int j = 0; j < 4; j++) {
            int idx = tid + j * 256;
            int r = idx >> 5, c4 = idx & 31;
            *(float4*)&Bs[r][c4 * 4] =
                *(const float4*)(W + (size_t)(k0 + r) * HID + c4 * 4);
        }
        __syncthreads();
#pragma unroll
        for (int kk = 0; kk < 32; kk++) {
            float a0 = As[kk][ty * 4 + 0];
            float a1 = As[kk][ty * 4 + 1];
            float a2 = As[kk][ty * 4 + 2];
            float a3 = As[kk][ty * 4 + 3];
            float4 b0 = *(float4*)&Bs[kk][tx * 8];
            float4 b1 = *(float4*)&Bs[kk][tx * 8 + 4];
            float bb[8] = {b0.x, b0.y, b0.z, b0.w, b1.x, b1.y, b1.z, b1.w};
#pragma unroll
            for (int j = 0; j < 8; j++) {
                acc[0][j] += a0 * bb[j];
                acc[1][j] += a1 * bb[j];
                acc[2][j] += a2 * bb[j];
                acc[3][j] += a3 * bb[j];
            }
        }
        __syncthreads();
    }
    float4 bi0 = *(const float4*)(B + tx * 8);
    float4 bi1 = *(const float4*)(B + tx * 8 + 4);
#pragma unroll
    for (int i = 0; i < 4; i++) {
        int row = blockRow + ty * 4 + i;
        if (row >= NN) continue;
        float4 o0 = make_float4(acc[i][0] + bi0.x, acc[i][1] + bi0.y,
                                acc[i][2] + bi0.z, acc[i][3] + bi0.w);
        float4 o1 = make_float4(acc[i][4] + bi1.x, acc[i][5] + bi1.y,
                                acc[i][6] + bi1.z, acc[i][7] + bi1.w);
        float* hp  = d_h  + (size_t)row * HID + tx * 8;
        float* h0p = d_h0 + (size_t)row * HID + tx * 8;
        *(float4*)(hp)      = o0;
        *(float4*)(hp + 4)  = o1;
        *(float4*)(h0p)     = o0;
        *(float4*)(h0p + 4) = o1;
    }
}

// ---------------- aggregation: s = (1-a)*(D^-1/2 A D^-1/2 h) + a*h0 ----------------
// one warp per node, float4 per lane (32 lanes x 16B = 512B row)
__global__ __launch_bounds__(256) void k_agg() {
    int warp = blockIdx.x * 8 + (threadIdx.x >> 5);
    if (warp >= NN) return;
    int lane = threadIdx.x & 31;
    const float4* h4 = (const float4*)d_h;
    const int i = warp;
    float di = d_dinv[i];
    float wself = di * di;
    float4 hi = h4[(size_t)i * 32 + lane];
    float ax = wself * hi.x, ay = wself * hi.y, az = wself * hi.z, aw = wself * hi.w;
    float bx = 0.f, by = 0.f, bz = 0.f, bw = 0.f;
    int beg = d_rowptr[i], end = d_rowptr[i + 1];
    int e = beg;
    for (; e + 1 < end; e += 2) {
        int   s0 = d_csr_src[e],   s1 = d_csr_src[e + 1];
        float w0 = d_csr_w[e],     w1 = d_csr_w[e + 1];
        float4 v0 = __ldg(&h4[(size_t)s0 * 32 + lane]);
        float4 v1 = __ldg(&h4[(size_t)s1 * 32 + lane]);
        ax += w0 * v0.x; ay += w0 * v0.y; az += w0 * v0.z; aw += w0 * v0.w;
        bx += w1 * v1.x; by += w1 * v1.y; bz += w1 * v1.z; bw += w1 * v1.w;
    }
    if (e < end) {
        int s0 = d_csr_src[e];
        float w0 = d_csr_w[e];
        float4 v0 = __ldg(&h4[(size_t)s0 * 32 + lane]);
        ax += w0 * v0.x; ay += w0 * v0.y; az += w0 * v0.z; aw += w0 * v0.w;
    }
    float4 h0v = ((const float4*)d_h0)[(size_t)i * 32 + lane];
    float4 o;
    o.x = (1.f - ALPHA_) * (ax + bx) + ALPHA_ * h0v.x;
    o.y = (1.f - ALPHA_) * (ay + by) + ALPHA_ * h0v.y;
    o.z = (1.f - ALPHA_) * (az + bz) + ALPHA_ * h0v.z;
    o.w = (1.f - ALPHA_) * (aw + bw) + ALPHA_ * h0v.w;
    ((float4*)d_s)[(size_t)i * 32 + lane] = o;
}

// ---------------- layer GEMM + identity-map mix + ELU ----------------
// h = elu((1-beta)*s + beta*(s @ W))
__global__ __launch_bounds__(256) void k_gemm_layer(const float* __restrict__ W,
                                                    float beta) {
    __shared__ float As[32][64];
    __shared__ float Bs[32][128];
    const int tid = threadIdx.x;
    const int blockRow = blockIdx.x * 64;
    const int tx = tid & 15, ty = tid >> 4;
    float acc[4][8];
#pragma unroll
    for (int i = 0; i < 4; i++)
#pragma unroll
        for (int j = 0; j < 8; j++) acc[i][j] = 0.f;

    for (int k0 = 0; k0 < HID; k0 += 32) {
#pragma unroll
        for (int j = 0; j < 2; j++) {
            int idx = tid + j * 256;
            int r = idx >> 3, c4 = idx & 7;
            int grow = blockRow + r;
            float4 v = make_float4(0.f, 0.f, 0.f, 0.f);
            if (grow < NN)
                v = *(const float4*)(d_s + (size_t)grow * HID + k0 + c4 * 4);
            As[c4 * 4 + 0][r] = v.x;
            As[c4 * 4 + 1][r] = v.y;
            As[c4 * 4 + 2][r] = v.z;
            As[c4 * 4 + 3][r] = v.w;
        }
#pragma unroll
        for (int j = 0; j < 4; j++) {
            int idx = tid + j * 256;
            int r = idx >> 5, c4 = idx & 31;
            *(float4*)&Bs[r][c4 * 4] =
                *(const float4*)(W + (size_t)(k0 + r) * HID + c4 * 4);
        }
        __syncthreads();
#pragma unroll
        for (int kk = 0; kk < 32; kk++) {
            float a0 = As[kk][ty * 4 + 0];
            float a1 = As[kk][ty * 4 + 1];
            float a2 = As[kk][ty * 4 + 2];
            float a3 = As[kk][ty * 4 + 3];
            float4 b0 = *(float4*)&Bs[kk][tx * 8];
            float4 b1 = *(float4*)&Bs[kk][tx * 8 + 4];
            float bb[8] = {b0.x, b0.y, b0.z, b0.w, b1.x, b1.y, b1.z, b1.w};
#pragma unroll
            for (int j = 0; j < 8; j++) {
                acc[0][j] += a0 * bb[j];
                acc[1][j] += a1 * bb[j];
                acc[2][j] += a2 * bb[j];
                acc[3][j] += a3 * bb[j];
            }
        }
        __syncthreads();
    }
    const float omb = 1.f - beta;
#pragma unroll
    for (int i = 0; i < 4; i++) {
        int row = blockRow + ty * 4 + i;
        if (row >= NN) continue;
        const float* sp = d_s + (size_t)row * HID + tx * 8;
        float4 s0 = *(const float4*)(sp);
        float4 s1 = *(const float4*)(sp + 4);
        float sv[8] = {s0.x, s0.y, s0.z, s0.w, s1.x, s1.y, s1.z, s1.w};
        float ov[8];
#pragma unroll
        for (int j = 0; j < 8; j++) {
            float v = omb * sv[j] + beta * acc[i][j];
            ov[j] = (v > 0.f) ? v : expm1f(v);
        }
        float* hp = d_h + (size_t)row * HID + tx * 8;
        *(float4*)(hp)     = make_float4(ov[0], ov[1], ov[2], ov[3]);
        *(float4*)(hp + 4) = make_float4(ov[4], ov[5], ov[6], ov[7]);
    }
}

// ---------------- output GEMM + log_softmax ----------------
// block = 256 threads = 8 warps; block handles 32 rows, warp handles 4 rows,
// lane holds cols {lane, lane+32}
__global__ __launch_bounds__(256) void k_out(const float* __restrict__ Wo,
                                             const float* __restrict__ Bo,
                                             float* __restrict__ out) {
    __shared__ float ws[128][64];   // 32 KB
    __shared__ float hs[32][128];   // 16 KB
    const int tid = threadIdx.x;
    const int base = blockIdx.x * 32;
    // load Wo (2048 float4, 8/thread)
#pragma unroll
    for (int j = 0; j < 8; j++) {
        int idx = tid + j * 256;
        int r = idx >> 4, c4 = idx & 15;
        *(float4*)&ws[r][c4 * 4] = *(const float4*)(Wo + (size_t)r * NC + c4 * 4);
    }
    // load 32 h rows (1024 float4, 4/thread)
#pragma unroll
    for (int j = 0; j < 4; j++) {
        int idx = tid + j * 256;
        int r = idx >> 5, c4 = idx & 31;
        *(float4*)&hs[r][c4 * 4] =
            *(const float4*)(d_h + (size_t)(base + r) * HID + c4 * 4);
    }
    __syncthreads();
    const int w = tid >> 5, lane = tid & 31;
    float b0 = Bo[lane], b1 = Bo[lane + 32];
    float acc[4][2];
#pragma unroll
    for (int r = 0; r < 4; r++) { acc[r][0] = 0.f; acc[r][1] = 0.f; }
    for (int k = 0; k < HID; k++) {
        float wv0 = ws[k][lane];
        float wv1 = ws[k][lane + 32];
#pragma unroll
        for (int r = 0; r < 4; r++) {
            float hv = hs[w * 4 + r][k];
            acc[r][0] += hv * wv0;
            acc[r][1] += hv * wv1;
        }
    }
#pragma unroll
    for (int r = 0; r < 4; r++) {
        int row = base + w * 4 + r;
        float v0 = acc[r][0] + b0;
        float v1 = acc[r][1] + b1;
        float m = fmaxf(v0, v1);
#pragma unroll
        for (int off = 16; off; off >>= 1)
            m = fmaxf(m, __shfl_xor_sync(0xffffffff, m, off));
        float ssum = expf(v0 - m) + expf(v1 - m);
#pragma unroll
        for (int off = 16; off; off >>= 1)
            ssum += __shfl_xor_sync(0xffffffff, ssum, off);
        float lse = m + logf(ssum);
        out[(size_t)row * NC + lane]      = v0 - lse;
        out[(size_t)row * NC + lane + 32] = v1 - lse;
    }
}

// ---------------- launch ----------------
extern "C" void kernel_launch(void* const* d_in, const int* in_sizes, int n_in,
                              void* d_out, int out_size) {
    const float* x      = (const float*)d_in[0];
    const void*  ei     = d_in[1];
    const float* w_in   = (const float*)d_in[2];
    const float* b_in   = (const float*)d_in[3];
    const float* conv_w = (const float*)d_in[4];
    const float* w_out  = (const float*)d_in[5];
    const float* b_out  = (const float*)d_in[6];
    float*       out    = (float*)d_out;

    k_detect<<<1, 32>>>(ei);
    k_zero<<<(NN + 255) / 256, 256>>>();
    k_prep_edges<<<(NE + 255) / 256, 256>>>(ei);
    k_dinv<<<(NN + 255) / 256, 256>>>();
    k_scan<<<1, 1024>>>();
    k_scatter<<<(NE + 255) / 256, 256>>>();

    k_gemm_in<<<(NN + 63) / 64, 256>>>(x, w_in, b_in);

    for (int l = 0; l < NL; l++) {
        float beta = (float)log(0.5 / (double)(l + 1) + 1.0);
        k_agg<<<(NN + 7) / 8, 256>>>();
        k_gemm_layer<<<(NN + 63) / 64, 256>>>(conv_w + (size_t)l * HID * HID, beta);
    }

    k_out<<<NN / 32, 256>>>(w_out, b_out, out);
}

// round 4
// speedup vs baseline: 1.0136x; 1.0136x over previous
#include <cuda_runtime.h>
#include <math.h>

// Problem constants (GCNII_30794915512599)
#define NN   100000      // nodes
#define NE   1600000     // edges
#define FIN  512
#define HID  128
#define NC   64
#define NL   8

// ---------------- scratch (static __device__ — no allocations) ----------------
__device__ int   d_cnt[NN];
__device__ int   d_fill[NN];
__device__ int   d_rowptr[NN + 1];
__device__ float d_dinv[NN];
__device__ int   d_src[NE];
__device__ int   d_dst[NE];
__device__ int   d_csr_src[NE];
__device__ float d_csr_w[NE];
__device__ float d_h [(size_t)NN * HID];
__device__ float d_h0[(size_t)NN * HID];
__device__ int   d_is64;

// ---------------- init: edge dtype detection + counter zeroing ----------------
// edge_index is logically int64 in the reference, but JAX without x64 emits
// int32. Interpreting int32 pairs as uint64 gives values >= 2^32 whenever the
// high word (another node index) is nonzero; true int64 indices are < 100000.
__global__ __launch_bounds__(256) void k_init(const void* p) {
    int i = blockIdx.x * blockDim.x + threadIdx.x;
    if (i < NN) { d_cnt[i] = 0; d_fill[i] = 0; }
    if (blockIdx.x == 0 && threadIdx.x < 32) {
        const unsigned long long* q = (const unsigned long long*)p;
        bool any_big = false;
        for (int k = threadIdx.x; k < 2048; k += 32)
            if (q[k] > 0xFFFFFFFFull) any_big = true;
        any_big = __any_sync(0xffffffff, any_big);
        if (threadIdx.x == 0) d_is64 = any_big ? 0 : 1;
    }
}

__global__ __launch_bounds__(256) void k_prep_edges(const void* eiv) {
    int e = blockIdx.x * blockDim.x + threadIdx.x;
    if (e >= NE) return;
    int s, d;
    if (d_is64) {
        const long long* ei = (const long long*)eiv;
        s = (int)ei[e];
        d = (int)ei[(size_t)NE + e];
    } else {
        const int* ei = (const int*)eiv;
        s = ei[e];
        d = ei[NE + e];
    }
    s = min(max(s, 0), NN - 1);
    d = min(max(d, 0), NN - 1);
    d_src[e] = s;
    d_dst[e] = d;
    atomicAdd(&d_cnt[d], 1);
}

// single-block exclusive scan over d_cnt -> d_rowptr, fused with dinv compute
__global__ __launch_bounds__(1024) void k_scan_dinv() {
    __shared__ int buf[1024];
    const int t = threadIdx.x;
    const int CH = (NN + 1023) / 1024;   // 98
    const int start = t * CH;
    int s = 0;
    for (int j = 0; j < CH; j++) {
        int idx = start + j;
        if (idx < NN) s += d_cnt[idx];
    }
    buf[t] = s;
    __syncthreads();
    for (int off = 1; off < 1024; off <<= 1) {
        int v = (t >= off) ? buf[t - off] : 0;
        __syncthreads();
        buf[t] += v;
        __syncthreads();
    }
    int run = (t == 0) ? 0 : buf[t - 1];
    for (int j = 0; j < CH; j++) {
        int idx = start + j;
        if (idx < NN) {
            int c = d_cnt[idx];
            d_rowptr[idx] = run;
            d_dinv[idx] = rsqrtf((float)(c + 1));   // +1 self loop
            run += c;
        }
    }
    if (t == 1023) d_rowptr[NN] = buf[1023];
}

__global__ __launch_bounds__(256) void k_scatter() {
    int e = blockIdx.x * blockDim.x + threadIdx.x;
    if (e >= NE) return;
    int s = d_src[e], d = d_dst[e];
    int pos = d_rowptr[d] + atomicAdd(&d_fill[d], 1);
    d_csr_src[pos] = s;
    d_csr_w[pos]   = d_dinv[s] * d_dinv[d];
}

// ---------------- input GEMM: h = x @ w_in + b_in ; h0 = h ----------------
// BM=128, BN=128, BK=16, 256 threads, thread tile 8x8
__global__ __launch_bounds__(256) void k_gemm_in(const float* __restrict__ X,
                                                 const float* __restrict__ W,
                                                 const float* __restrict__ B) {
    __shared__ float As[16][132];   // transposed A tile, padded
    __shared__ float Bs[16][128];
    const int tid = threadIdx.x;
    const int blockRow = blockIdx.x * 128;
    const int tx = tid & 15, ty = tid >> 4;
    float acc[8][8];
#pragma unroll
    for (int i = 0; i < 8; i++)
#pragma unroll
        for (int j = 0; j < 8; j++) acc[i][j] = 0.f;

    for (int k0 = 0; k0 < FIN; k0 += 16) {
        // A tile: 128 rows x 16 k (512 float4, 2/thread)
#pragma unroll
        for (int j = 0; j < 2; j++) {
            int idx = tid + j * 256;
            int r = idx >> 2, c4 = idx & 3;
            int grow = blockRow + r;
            float4 v = make_float4(0.f, 0.f, 0.f, 0.f);
            if (grow < NN)
                v = *(const float4*)(X + (size_t)grow * FIN + k0 + c4 * 4);
            As[c4 * 4 + 0][r] = v.x;
            As[c4 * 4 + 1][r] = v.y;
            As[c4 * 4 + 2][r] = v.z;
            As[c4 * 4 + 3][r] = v.w;
        }
        // B tile: 16 x 128 (512 float4, 2/thread)
#pragma unroll
        for (int j = 0; j < 2; j++) {
            int idx = tid + j * 256;
            int r = idx >> 5, c4 = idx & 31;
            *(float4*)&Bs[r][c4 * 4] =
                *(const float4*)(W + (size_t)(k0 + r) * HID + c4 * 4);
        }
        __syncthreads();
#pragma unroll
        for (int kk = 0; kk < 16; kk++) {
            float a[8], b[8];
            *(float4*)&a[0] = *(float4*)&As[kk][ty * 8];
            *(float4*)&a[4] = *(float4*)&As[kk][ty * 8 + 4];
            *(float4*)&b[0] = *(float4*)&Bs[kk][tx * 8];
            *(float4*)&b[4] = *(float4*)&Bs[kk][tx * 8 + 4];
#pragma unroll
            for (int i = 0; i < 8; i++)
#pragma unroll
                for (int j = 0; j < 8; j++)
                    acc[i][j] += a[i] * b[j];
        }
        __syncthreads();
    }
    float bi[8];
    *(float4*)&bi[0] = *(const float4*)(B + tx * 8);
    *(float4*)&bi[4] = *(const float4*)(B + tx * 8 + 4);
#pragma unroll
    for (int i = 0; i < 8; i++) {
        int row = blockRow + ty * 8 + i;
        if (row >= NN) continue;
        float4 o0 = make_float4(acc[i][0] + bi[0], acc[i][1] + bi[1],
                                acc[i][2] + bi[2], acc[i][3] + bi[3]);
        float4 o1 = make_float4(acc[i][4] + bi[4], acc[i][5] + bi[5],
                                acc[i][6] + bi[6], acc[i][7] + bi[7]);
        float* hp  = d_h  + (size_t)row * HID + tx * 8;
        float* h0p = d_h0 + (size_t)row * HID + tx * 8;
        *(float4*)(hp)      = o0;
        *(float4*)(hp + 4)  = o1;
        *(float4*)(h0p)     = o0;
        *(float4*)(h0p + 4) = o1;
    }
}

// ---------------- fused layer: aggregate + mix + GEMM + ELU ----------------
// h = elu((1-beta)*s + beta*(s @ W)), s = 0.9*(norm-adj @ h) + 0.1*h0
// Block owns 64 rows. Phase A: warp-per-row gather into smem s-tile.
// Phase B: 64x128x128 GEMM from smem, epilogue mix+ELU, write d_h.
__global__ __launch_bounds__(256) void k_layer(const float* __restrict__ W,
                                               float beta) {
    __shared__ float st[64][130];   // s tile [row][k], pad 2 (33280 B)
    __shared__ float Bs[16][128];   // W tile (8192 B)
    const int tid = threadIdx.x;
    const int blockRow = blockIdx.x * 64;
    const int w = tid >> 5, lane = tid & 31;

    // ---- Phase A: aggregation ----
    const float4* h4 = (const float4*)d_h;
#pragma unroll 1
    for (int r8 = 0; r8 < 8; r8++) {
        int rl = w * 8 + r8;
        int i = blockRow + rl;
        float ox = 0.f, oy = 0.f, oz = 0.f, ow = 0.f;
        if (i < NN) {
            float di = d_dinv[i];
            float wself = di * di;
            float4 hi = h4[(size_t)i * 32 + lane];
            float ax = wself * hi.x, ay = wself * hi.y;
            float az = wself * hi.z, aw = wself * hi.w;
            float bx = 0.f, by = 0.f, bz = 0.f, bw = 0.f;
            int beg = d_rowptr[i], end = d_rowptr[i + 1];
            int e = beg;
            for (; e + 1 < end; e += 2) {
                int   s0 = d_csr_src[e],   s1 = d_csr_src[e + 1];
                float w0 = d_csr_w[e],     w1 = d_csr_w[e + 1];
                float4 v0 = __ldg(&h4[(size_t)s0 * 32 + lane]);
                float4 v1 = __ldg(&h4[(size_t)s1 * 32 + lane]);
                ax += w0 * v0.x; ay += w0 * v0.y; az += w0 * v0.z; aw += w0 * v0.w;
                bx += w1 * v1.x; by += w1 * v1.y; bz += w1 * v1.z; bw += w1 * v1.w;
            }
            if (e < end) {
                int s0 = d_csr_src[e];
                float w0 = d_csr_w[e];
                float4 v0 = __ldg(&h4[(size_t)s0 * 32 + lane]);
                ax += w0 * v0.x; ay += w0 * v0.y; az += w0 * v0.z; aw += w0 * v0.w;
            }
            float4 h0v = ((const float4*)d_h0)[(size_t)i * 32 + lane];
            ox = 0.9f * (ax + bx) + 0.1f * h0v.x;
            oy = 0.9f * (ay + by) + 0.1f * h0v.y;
            oz = 0.9f * (az + bz) + 0.1f * h0v.z;
            ow = 0.9f * (aw + bw) + 0.1f * h0v.w;
        }
        st[rl][lane * 4 + 0] = ox;
        st[rl][lane * 4 + 1] = oy;
        st[rl][lane * 4 + 2] = oz;
        st[rl][lane * 4 + 3] = ow;
    }
    __syncthreads();

    // ---- Phase B: GEMM from smem ----
    const int tx = tid & 15, ty = tid >> 4;
    float acc[4][8];
#pragma unroll
    for (int i = 0; i < 4; i++)
#pragma unroll
        for (int j = 0; j < 8; j++) acc[i][j] = 0.f;

    for (int k0 = 0; k0 < HID; k0 += 16) {
#pragma unroll
        for (int j = 0; j < 2; j++) {
            int idx = tid + j * 256;
            int r = idx >> 5, c4 = idx & 31;
            *(float4*)&Bs[r][c4 * 4] =
                *(const float4*)(W + (size_t)(k0 + r) * HID + c4 * 4);
        }
        __syncthreads();
#pragma unroll
        for (int kk = 0; kk < 16; kk++) {
            float a0 = st[ty * 4 + 0][k0 + kk];
            float a1 = st[ty * 4 + 1][k0 + kk];
            float a2 = st[ty * 4 + 2][k0 + kk];
            float a3 = st[ty * 4 + 3][k0 + kk];
            float b[8];
            *(float4*)&b[0] = *(float4*)&Bs[kk][tx * 8];
            *(float4*)&b[4] = *(float4*)&Bs[kk][tx * 8 + 4];
#pragma unroll
            for (int j = 0; j < 8; j++) {
                acc[0][j] += a0 * b[j];
                acc[1][j] += a1 * b[j];
                acc[2][j] += a2 * b[j];
                acc[3][j] += a3 * b[j];
            }
        }
        __syncthreads();
    }

    // ---- epilogue: mix + ELU ----
    const float omb = 1.f - beta;
#pragma unroll
    for (int i = 0; i < 4; i++) {
        int rl = ty * 4 + i;
        int row = blockRow + rl;
        if (row >= NN) continue;
        float ov[8];
#pragma unroll
        for (int j = 0; j < 8; j++) {
            float sv = st[rl][tx * 8 + j];
            float v = omb * sv + beta * acc[i][j];
            ov[j] = (v > 0.f) ? v : expm1f(v);
        }
        float* hp = d_h + (size_t)row * HID + tx * 8;
        *(float4*)(hp)     = make_float4(ov[0], ov[1], ov[2], ov[3]);
        *(float4*)(hp + 4) = make_float4(ov[4], ov[5], ov[6], ov[7]);
    }
}

// ---------------- output GEMM + log_softmax ----------------
__global__ __launch_bounds__(256) void k_out(const float* __restrict__ Wo,
                                             const float* __restrict__ Bo,
                                             float* __restrict__ out) {
    __shared__ float ws[128][64];   // 32 KB
    __shared__ float hs[32][128];   // 16 KB
    const int tid = threadIdx.x;
    const int base = blockIdx.x * 32;
#pragma unroll
    for (int j = 0; j < 8; j++) {
        int idx = tid + j * 256;
        int r = idx >> 4, c4 = idx & 15;
        *(float4*)&ws[r][c4 * 4] = *(const float4*)(Wo + (size_t)r * NC + c4 * 4);
    }
#pragma unroll
    for (int j = 0; j < 4; j++) {
        int idx = tid + j * 256;
        int r = idx >> 5, c4 = idx & 31;
        *(float4*)&hs[r][c4 * 4] =
            *(const float4*)(d_h + (size_t)(base + r) * HID + c4 * 4);
    }
    __syncthreads();
    const int w = tid >> 5, lane = tid & 31;
    float b0 = Bo[lane], b1 = Bo[lane + 32];
    float acc[4][2];
#pragma unroll
    for (int r = 0; r < 4; r++) { acc[r][0] = 0.f; acc[r][1] = 0.f; }
    for (int k = 0; k < HID; k++) {
        float wv0 = ws[k][lane];
        float wv1 = ws[k][lane + 32];
#pragma unroll
        for (int r = 0; r < 4; r++) {
            float hv = hs[w * 4 + r][k];
            acc[r][0] += hv * wv0;
            acc[r][1] += hv * wv1;
        }
    }
#pragma unroll
    for (int r = 0; r < 4; r++) {
        int row = base + w * 4 + r;
        float v0 = acc[r][0] + b0;
        float v1 = acc[r][1] + b1;
        float m = fmaxf(v0, v1);
#pragma unroll
        for (int off = 16; off; off >>= 1)
            m = fmaxf(m, __shfl_xor_sync(0xffffffff, m, off));
        float ssum = expf(v0 - m) + expf(v1 - m);
#pragma unroll
        for (int off = 16; off; off >>= 1)
            ssum += __shfl_xor_sync(0xffffffff, ssum, off);
        float lse = m + logf(ssum);
        out[(size_t)row * NC + lane]      = v0 - lse;
        out[(size_t)row * NC + lane + 32] = v1 - lse;
    }
}

// ---------------- launch ----------------
extern "C" void kernel_launch(void* const* d_in, const int* in_sizes, int n_in,
                              void* d_out, int out_size) {
    const float* x      = (const float*)d_in[0];
    const void*  ei     = d_in[1];
    const float* w_in   = (const float*)d_in[2];
    const float* b_in   = (const float*)d_in[3];
    const float* conv_w = (const float*)d_in[4];
    const float* w_out  = (const float*)d_in[5];
    const float* b_out  = (const float*)d_in[6];
    float*       out    = (float*)d_out;

    k_init<<<(NN + 255) / 256, 256>>>(ei);
    k_prep_edges<<<(NE + 255) / 256, 256>>>(ei);
    k_scan_dinv<<<1, 1024>>>();
    k_scatter<<<(NE + 255) / 256, 256>>>();

    k_gemm_in<<<(NN + 127) / 128, 256>>>(x, w_in, b_in);

    for (int l = 0; l < NL; l++) {
        float beta = (float)log(0.5 / (double)(l + 1) + 1.0);
        k_layer<<<(NN + 63) / 64, 256>>>(conv_w + (size_t)l * HID * HID, beta);
    }

    k_out<<<NN / 32, 256>>>(w_out, b_out, out);
}

// round 5
// speedup vs baseline: 1.0735x; 1.0591x over previous
#include <cuda_runtime.h>
#include <math.h>

// Problem constants (GCNII_30794915512599)
#define NN   100000      // nodes
#define NE   1600000     // edges
#define FIN  512
#define HID  128
#define NC   64
#define NL   8

// ---------------- scratch (static __device__ — no allocations) ----------------
__device__ int   d_cnt[NN];
__device__ int   d_fill[NN];
__device__ int   d_rowptr[NN + 1];
__device__ float d_dinv[NN];
__device__ int   d_src[NE];
__device__ int   d_dst[NE];
__device__ int2  d_epack[NE];    // packed (src, weight-as-int)
__device__ float d_h [(size_t)NN * HID];
__device__ float d_h0[(size_t)NN * HID];
__device__ float d_s [(size_t)NN * HID];
__device__ int   d_is64;

// ---------------- init: edge dtype detection + counter zeroing ----------------
// edge_index is logically int64 in the reference, but JAX without x64 emits
// int32. int32 pairs read as uint64 are >= 2^32 whenever the high word is
// nonzero; true int64 indices are < 100000.
__global__ __launch_bounds__(256) void k_init(const void* p) {
    int i = blockIdx.x * blockDim.x + threadIdx.x;
    if (i < NN) { d_cnt[i] = 0; d_fill[i] = 0; }
    if (blockIdx.x == 0 && threadIdx.x < 32) {
        const unsigned long long* q = (const unsigned long long*)p;
        bool any_big = false;
        for (int k = threadIdx.x; k < 2048; k += 32)
            if (q[k] > 0xFFFFFFFFull) any_big = true;
        any_big = __any_sync(0xffffffff, any_big);
        if (threadIdx.x == 0) d_is64 = any_big ? 0 : 1;
    }
}

__global__ __launch_bounds__(256) void k_prep_edges(const void* eiv) {
    int e = blockIdx.x * blockDim.x + threadIdx.x;
    if (e >= NE) return;
    int s, d;
    if (d_is64) {
        const long long* ei = (const long long*)eiv;
        s = (int)ei[e];
        d = (int)ei[(size_t)NE + e];
    } else {
        const int* ei = (const int*)eiv;
        s = ei[e];
        d = ei[NE + e];
    }
    s = min(max(s, 0), NN - 1);
    d = min(max(d, 0), NN - 1);
    d_src[e] = s;
    d_dst[e] = d;
    atomicAdd(&d_cnt[d], 1);
}

// single-block exclusive scan over d_cnt -> d_rowptr, fused with dinv compute
__global__ __launch_bounds__(1024) void k_scan_dinv() {
    __shared__ int buf[1024];
    const int t = threadIdx.x;
    const int CH = (NN + 1023) / 1024;   // 98
    const int start = t * CH;
    int s = 0;
    for (int j = 0; j < CH; j++) {
        int idx = start + j;
        if (idx < NN) s += d_cnt[idx];
    }
    buf[t] = s;
    __syncthreads();
    for (int off = 1; off < 1024; off <<= 1) {
        int v = (t >= off) ? buf[t - off] : 0;
        __syncthreads();
        buf[t] += v;
        __syncthreads();
    }
    int run = (t == 0) ? 0 : buf[t - 1];
    for (int j = 0; j < CH; j++) {
        int idx = start + j;
        if (idx < NN) {
            int c = d_cnt[idx];
            d_rowptr[idx] = run;
            d_dinv[idx] = rsqrtf((float)(c + 1));   // +1 self loop
            run += c;
        }
    }
    if (t == 1023) d_rowptr[NN] = buf[1023];
}

__global__ __launch_bounds__(256) void k_scatter() {
    int e = blockIdx.x * blockDim.x + threadIdx.x;
    if (e >= NE) return;
    int s = d_src[e], d = d_dst[e];
    int pos = d_rowptr[d] + atomicAdd(&d_fill[d], 1);
    float w = d_dinv[s] * d_dinv[d];
    d_epack[pos] = make_int2(s, __float_as_int(w));
}

// ---------------- input GEMM: h = x @ w_in + b_in ; h0 = h ----------------
// BM=128, BN=128, BK=16, 256 threads, thread tile 8x8
__global__ __launch_bounds__(256) void k_gemm_in(const float* __restrict__ X,
                                                 const float* __restrict__ W,
                                                 const float* __restrict__ B) {
    __shared__ float As[16][132];   // transposed A tile, padded
    __shared__ float Bs[16][128];
    const int tid = threadIdx.x;
    const int blockRow = blockIdx.x * 128;
    const int tx = tid & 15, ty = tid >> 4;
    float acc[8][8];
#pragma unroll
    for (int i = 0; i < 8; i++)
#pragma unroll
        for (int j = 0; j < 8; j++) acc[i][j] = 0.f;

    for (int k0 = 0; k0 < FIN; k0 += 16) {
#pragma unroll
        for (int j = 0; j < 2; j++) {
            int idx = tid + j * 256;
            int r = idx >> 2, c4 = idx & 3;
            int grow = blockRow + r;
            float4 v = make_float4(0.f, 0.f, 0.f, 0.f);
            if (grow < NN)
                v = *(const float4*)(X + (size_t)grow * FIN + k0 + c4 * 4);
            As[c4 * 4 + 0][r] = v.x;
            As[c4 * 4 + 1][r] = v.y;
            As[c4 * 4 + 2][r] = v.z;
            As[c4 * 4 + 3][r] = v.w;
        }
#pragma unroll
        for (int j = 0; j < 2; j++) {
            int idx = tid + j * 256;
            int r = idx >> 5, c4 = idx & 31;
            *(float4*)&Bs[r][c4 * 4] =
                *(const float4*)(W + (size_t)(k0 + r) * HID + c4 * 4);
        }
        __syncthreads();
#pragma unroll
        for (int kk = 0; kk < 16; kk++) {
            float a[8], b[8];
            *(float4*)&a[0] = *(float4*)&As[kk][ty * 8];
            *(float4*)&a[4] = *(float4*)&As[kk][ty * 8 + 4];
            *(float4*)&b[0] = *(float4*)&Bs[kk][tx * 8];
            *(float4*)&b[4] = *(float4*)&Bs[kk][tx * 8 + 4];
#pragma unroll
            for (int i = 0; i < 8; i++)
#pragma unroll
                for (int j = 0; j < 8; j++)
                    acc[i][j] += a[i] * b[j];
        }
        __syncthreads();
    }
    float bi[8];
    *(float4*)&bi[0] = *(const float4*)(B + tx * 8);
    *(float4*)&bi[4] = *(const float4*)(B + tx * 8 + 4);
#pragma unroll
    for (int i = 0; i < 8; i++) {
        int row = blockRow + ty * 8 + i;
        if (row >= NN) continue;
        float4 o0 = make_float4(acc[i][0] + bi[0], acc[i][1] + bi[1],
                                acc[i][2] + bi[2], acc[i][3] + bi[3]);
        float4 o1 = make_float4(acc[i][4] + bi[4], acc[i][5] + bi[5],
                                acc[i][6] + bi[6], acc[i][7] + bi[7]);
        float* hp  = d_h  + (size_t)row * HID + tx * 8;
        float* h0p = d_h0 + (size_t)row * HID + tx * 8;
        *(float4*)(hp)      = o0;
        *(float4*)(hp + 4)  = o1;
        *(float4*)(h0p)     = o0;
        *(float4*)(h0p + 4) = o1;
    }
}

// ---------------- aggregation: s = 0.9*(norm-adj @ h) + 0.1*h0 ----------------
// one warp per node, float4 per lane, 4-way edge unroll (MLP=4)
__global__ __launch_bounds__(256) void k_agg() {
    int i = blockIdx.x * 8 + (threadIdx.x >> 5);
    if (i >= NN) return;
    int lane = threadIdx.x & 31;
    const float4* h4 = (const float4*)d_h;
    float di = d_dinv[i];
    float wself = di * di;
    float4 hi = h4[(size_t)i * 32 + lane];
    float a0x = wself * hi.x, a0y = wself * hi.y;
    float a0z = wself * hi.z, a0w = wself * hi.w;
    float a1x = 0.f, a1y = 0.f, a1z = 0.f, a1w = 0.f;
    float a2x = 0.f, a2y = 0.f, a2z = 0.f, a2w = 0.f;
    float a3x = 0.f, a3y = 0.f, a3z = 0.f, a3w = 0.f;
    int beg = d_rowptr[i], end = d_rowptr[i + 1];
    int e = beg;
    int end4 = beg + ((end - beg) & ~3);
    for (; e < end4; e += 4) {
        int2 p0 = d_epack[e];
        int2 p1 = d_epack[e + 1];
        int2 p2 = d_epack[e + 2];
        int2 p3 = d_epack[e + 3];
        float4 v0 = __ldg(&h4[(size_t)p0.x * 32 + lane]);
        float4 v1 = __ldg(&h4[(size_t)p1.x * 32 + lane]);
        float4 v2 = __ldg(&h4[(size_t)p2.x * 32 + lane]);
        float4 v3 = __ldg(&h4[(size_t)p3.x * 32 + lane]);
        float w0 = __int_as_float(p0.y), w1 = __int_as_float(p1.y);
        float w2 = __int_as_float(p2.y), w3 = __int_as_float(p3.y);
        a0x += w0 * v0.x; a0y += w0 * v0.y; a0z += w0 * v0.z; a0w += w0 * v0.w;
        a1x += w1 * v1.x; a1y += w1 * v1.y; a1z += w1 * v1.z; a1w += w1 * v1.w;
        a2x += w2 * v2.x; a2y += w2 * v2.y; a2z += w2 * v2.z; a2w += w2 * v2.w;
        a3x += w3 * v3.x; a3y += w3 * v3.y; a3z += w3 * v3.z; a3w += w3 * v3.w;
    }
    for (; e < end; e++) {
        int2 p0 = d_epack[e];
        float w0 = __int_as_float(p0.y);
        float4 v0 = __ldg(&h4[(size_t)p0.x * 32 + lane]);
        a1x += w0 * v0.x; a1y += w0 * v0.y; a1z += w0 * v0.z; a1w += w0 * v0.w;
    }
    float4 h0v = ((const float4*)d_h0)[(size_t)i * 32 + lane];
    float4 o;
    o.x = 0.9f * ((a0x + a1x) + (a2x + a3x)) + 0.1f * h0v.x;
    o.y = 0.9f * ((a0y + a1y) + (a2y + a3y)) + 0.1f * h0v.y;
    o.z = 0.9f * ((a0z + a1z) + (a2z + a3z)) + 0.1f * h0v.z;
    o.w = 0.9f * ((a0w + a1w) + (a2w + a3w)) + 0.1f * h0v.w;
    ((float4*)d_s)[(size_t)i * 32 + lane] = o;
}

// ---------------- layer GEMM + identity-map mix + ELU ----------------
// h = elu((1-beta)*s + beta*(s @ W)); BM=128, BN=128, BK=16, 8x8 tiles
__global__ __launch_bounds__(256) void k_gemm_layer(const float* __restrict__ W,
                                                    float beta) {
    __shared__ float As[16][132];
    __shared__ float Bs[16][128];
    const int tid = threadIdx.x;
    const int blockRow = blockIdx.x * 128;
    const int tx = tid & 15, ty = tid >> 4;
    float acc[8][8];
#pragma unroll
    for (int i = 0; i < 8; i++)
#pragma unroll
        for (int j = 0; j < 8; j++) acc[i][j] = 0.f;

    for (int k0 = 0; k0 < HID; k0 += 16) {
#pragma unroll
        for (int j = 0; j < 2; j++) {
            int idx = tid + j * 256;
            int r = idx >> 2, c4 = idx & 3;
            int grow = blockRow + r;
            float4 v = make_float4(0.f, 0.f, 0.f, 0.f);
            if (grow < NN)
                v = *(const float4*)(d_s + (size_t)grow * HID + k0 + c4 * 4);
            As[c4 * 4 + 0][r] = v.x;
            As[c4 * 4 + 1][r] = v.y;
            As[c4 * 4 + 2][r] = v.z;
            As[c4 * 4 + 3][r] = v.w;
        }
#pragma unroll
        for (int j = 0; j < 2; j++) {
            int idx = tid + j * 256;
            int r = idx >> 5, c4 = idx & 31;
            *(float4*)&Bs[r][c4 * 4] =
                *(const float4*)(W + (size_t)(k0 + r) * HID + c4 * 4);
        }
        __syncthreads();
#pragma unroll
        for (int kk = 0; kk < 16; kk++) {
            float a[8], b[8];
            *(float4*)&a[0] = *(float4*)&As[kk][ty * 8];
            *(float4*)&a[4] = *(float4*)&As[kk][ty * 8 + 4];
            *(float4*)&b[0] = *(float4*)&Bs[kk][tx * 8];
            *(float4*)&b[4] = *(float4*)&Bs[kk][tx * 8 + 4];
#pragma unroll
            for (int i = 0; i < 8; i++)
#pragma unroll
                for (int j = 0; j < 8; j++)
                    acc[i][j] += a[i] * b[j];
        }
        __syncthreads();
    }

    const float omb = 1.f - beta;
#pragma unroll
    for (int i = 0; i < 8; i++) {
        int row = blockRow + ty * 8 + i;
        if (row >= NN) continue;
        const float* sp = d_s + (size_t)row * HID + tx * 8;
        float4 s0 = *(const float4*)(sp);
        float4 s1 = *(const float4*)(sp + 4);
        float sv[8] = {s0.x, s0.y, s0.z, s0.w, s1.x, s1.y, s1.z, s1.w};
        float ov[8];
#pragma unroll
        for (int j = 0; j < 8; j++) {
            float v = omb * sv[j] + beta * acc[i][j];
            ov[j] = (v > 0.f) ? v : expm1f(v);
        }
        float* hp = d_h + (size_t)row * HID + tx * 8;
        *(float4*)(hp)     = make_float4(ov[0], ov[1], ov[2], ov[3]);
        *(float4*)(hp + 4) = make_float4(ov[4], ov[5], ov[6], ov[7]);
    }
}

// ---------------- output GEMM + log_softmax ----------------
__global__ __launch_bounds__(256) void k_out(const float* __restrict__ Wo,
                                             const float* __restrict__ Bo,
                                             float* __restrict__ out) {
    __shared__ float ws[128][64];   // 32 KB
    __shared__ float hs[32][128];   // 16 KB
    const int tid = threadIdx.x;
    const int base = blockIdx.x * 32;
#pragma unroll
    for (int j = 0; j < 8; j++) {
        int idx = tid + j * 256;
        int r = idx >> 4, c4 = idx & 15;
        *(float4*)&ws[r][c4 * 4] = *(const float4*)(Wo + (size_t)r * NC + c4 * 4);
    }
#pragma unroll
    for (int j = 0; j < 4; j++) {
        int idx = tid + j * 256;
        int r = idx >> 5, c4 = idx & 31;
        *(float4*)&hs[r][c4 * 4] =
            *(const float4*)(d_h + (size_t)(base + r) * HID + c4 * 4);
    }
    __syncthreads();
    const int w = tid >> 5, lane = tid & 31;
    float b0 = Bo[lane], b1 = Bo[lane + 32];
    float acc[4][2];
#pragma unroll
    for (int r = 0; r < 4; r++) { acc[r][0] = 0.f; acc[r][1] = 0.f; }
    for (int k = 0; k < HID; k++) {
        float wv0 = ws[k][lane];
        float wv1 = ws[k][lane + 32];
#pragma unroll
        for (int r = 0; r < 4; r++) {
            float hv = hs[w * 4 + r][k];
            acc[r][0] += hv * wv0;
            acc[r][1] += hv * wv1;
        }
    }
#pragma unroll
    for (int r = 0; r < 4; r++) {
        int row = base + w * 4 + r;
        float v0 = acc[r][0] + b0;
        float v1 = acc[r][1] + b1;
        float m = fmaxf(v0, v1);
#pragma unroll
        for (int off = 16; off; off >>= 1)
            m = fmaxf(m, __shfl_xor_sync(0xffffffff, m, off));
        float ssum = expf(v0 - m) + expf(v1 - m);
#pragma unroll
        for (int off = 16; off; off >>= 1)
            ssum += __shfl_xor_sync(0xffffffff, ssum, off);
        float lse = m + logf(ssum);
        out[(size_t)row * NC + lane]      = v0 - lse;
        out[(size_t)row * NC + lane + 32] = v1 - lse;
    }
}

// ---------------- launch ----------------
extern "C" void kernel_launch(void* const* d_in, const int* in_sizes, int n_in,
                              void* d_out, int out_size) {
    const float* x      = (const float*)d_in[0];
    const void*  ei     = d_in[1];
    const float* w_in   = (const float*)d_in[2];
    const float* b_in   = (const float*)d_in[3];
    const float* conv_w = (const float*)d_in[4];
    const float* w_out  = (const float*)d_in[5];
    const float* b_out  = (const float*)d_in[6];
    float*       out    = (float*)d_out;

    // gemm_in placed 4th so the ncu window (4th launch) profiles it
    k_init<<<(NN + 255) / 256, 256>>>(ei);
    k_prep_edges<<<(NE + 255) / 256, 256>>>(ei);
    k_scan_dinv<<<1, 1024>>>();
    k_gemm_in<<<(NN + 127) / 128, 256>>>(x, w_in, b_in);
    k_scatter<<<(NE + 255) / 256, 256>>>();

    for (int l = 0; l < NL; l++) {
        float beta = (float)log(0.5 / (double)(l + 1) + 1.0);
        k_agg<<<(NN + 7) / 8, 256>>>();
        k_gemm_layer<<<(NN + 127) / 128, 256>>>(conv_w + (size_t)l * HID * HID, beta);
    }

    k_out<<<NN / 32, 256>>>(w_out, b_out, out);
}

// round 6
// speedup vs baseline: 1.1369x; 1.0590x over previous
#include <cuda_runtime.h>
#include <math.h>
#include <stdint.h>

// Problem constants (GCNII_30794915512599)
#define NN   100000      // nodes
#define NE   1600000     // edges
#define FIN  512
#define HID  128
#define NC   64
#define NL   8

// ---------------- scratch (static __device__ — no allocations) ----------------
__device__ int   d_cnt[NN];
__device__ int   d_fill[NN];
__device__ int   d_rowptr[NN + 1];
__device__ float d_dinv[NN];
__device__ int   d_src[NE];
__device__ int   d_dst[NE];
__device__ int2  d_epack[NE];    // packed (src, weight-as-int)
__device__ float d_h [(size_t)NN * HID];
__device__ float d_h0[(size_t)NN * HID];
__device__ float d_s [(size_t)NN * HID];
__device__ int   d_is64;

// ---------------- cp.async helpers ----------------
__device__ __forceinline__ void cp_async16(uint32_t saddr, const void* gptr) {
    asm volatile("cp.async.ca.shared.global [%0], [%1], 16;"
                 :: "r"(saddr), "l"(gptr));
}
__device__ __forceinline__ void cp_commit() {
    asm volatile("cp.async.commit_group;");
}
__device__ __forceinline__ void cp_wait0() {
    asm volatile("cp.async.wait_group 0;");
}
__device__ __forceinline__ uint32_t smem_u32(const void* p) {
    return (uint32_t)__cvta_generic_to_shared(p);
}

// ---------------- init: edge dtype detection + counter zeroing ----------------
// edge_index is logically int64 in the reference, but JAX without x64 emits
// int32. int32 pairs read as uint64 are >= 2^32 whenever the high word is
// nonzero; true int64 indices are < 100000.
__global__ __launch_bounds__(256) void k_init(const void* p) {
    int i = blockIdx.x * blockDim.x + threadIdx.x;
    if (i < NN) { d_cnt[i] = 0; d_fill[i] = 0; }
    if (blockIdx.x == 0 && threadIdx.x < 32) {
        const unsigned long long* q = (const unsigned long long*)p;
        bool any_big = false;
        for (int k = threadIdx.x; k < 2048; k += 32)
            if (q[k] > 0xFFFFFFFFull) any_big = true;
        any_big = __any_sync(0xffffffff, any_big);
        if (threadIdx.x == 0) d_is64 = any_big ? 0 : 1;
    }
}

__global__ __launch_bounds__(256) void k_prep_edges(const void* eiv) {
    int e = blockIdx.x * blockDim.x + threadIdx.x;
    if (e >= NE) return;
    int s, d;
    if (d_is64) {
        const long long* ei = (const long long*)eiv;
        s = (int)ei[e];
        d = (int)ei[(size_t)NE + e];
    } else {
        const int* ei = (const int*)eiv;
        s = ei[e];
        d = ei[NE + e];
    }
    s = min(max(s, 0), NN - 1);
    d = min(max(d, 0), NN - 1);
    d_src[e] = s;
    d_dst[e] = d;
    atomicAdd(&d_cnt[d], 1);
}

// single-block exclusive scan over d_cnt -> d_rowptr, fused with dinv compute
__global__ __launch_bounds__(1024) void k_scan_dinv() {
    __shared__ int buf[1024];
    const int t = threadIdx.x;
    const int CH = (NN + 1023) / 1024;   // 98
    const int start = t * CH;
    int s = 0;
    for (int j = 0; j < CH; j++) {
        int idx = start + j;
        if (idx < NN) s += d_cnt[idx];
    }
    buf[t] = s;
    __syncthreads();
    for (int off = 1; off < 1024; off <<= 1) {
        int v = (t >= off) ? buf[t - off] : 0;
        __syncthreads();
        buf[t] += v;
        __syncthreads();
    }
    int run = (t == 0) ? 0 : buf[t - 1];
    for (int j = 0; j < CH; j++) {
        int idx = start + j;
        if (idx < NN) {
            int c = d_cnt[idx];
            d_rowptr[idx] = run;
            d_dinv[idx] = rsqrtf((float)(c + 1));   // +1 self loop
            run += c;
        }
    }
    if (t == 1023) d_rowptr[NN] = buf[1023];
}

__global__ __launch_bounds__(256) void k_scatter() {
    int e = blockIdx.x * blockDim.x + threadIdx.x;
    if (e >= NE) return;
    int s = d_src[e], d = d_dst[e];
    int pos = d_rowptr[d] + atomicAdd(&d_fill[d], 1);
    float w = d_dinv[s] * d_dinv[d];
    d_epack[pos] = make_int2(s, __float_as_int(w));
}

// ---------------- input GEMM: h = x @ w_in + b_in ; h0 = h ----------------
// BM=128, BN=128, BK=16, 256 threads, 8x8 tiles, double-buffered + cp.async B
__global__ __launch_bounds__(256, 2) void k_gemm_in(const float* __restrict__ X,
                                                    const float* __restrict__ W,
                                                    const float* __restrict__ B) {
    __shared__ float As[2][16][132];
    __shared__ float Bs[2][16][128];
    const int tid = threadIdx.x;
    const int blockRow = blockIdx.x * 128;
    const int tx = tid & 15, ty = tid >> 4;

    // per-thread load coords
    const int ar = tid >> 2, ac4 = tid & 3;         // A: rows [ar, ar+64], k-col ac4*4
    const int br = tid >> 5, bc4 = tid & 31;        // B: rows [br, br+8],  col bc4*4

    float acc[8][8];
#pragma unroll
    for (int i = 0; i < 8; i++)
#pragma unroll
        for (int j = 0; j < 8; j++) acc[i][j] = 0.f;

    // ---- prologue: tile 0 into buffer 0 ----
    {
#pragma unroll
        for (int j = 0; j < 2; j++) {
            int r = ar + j * 64;
            int grow = blockRow + r;
            float4 v = make_float4(0.f, 0.f, 0.f, 0.f);
            if (grow < NN)
                v = *(const float4*)(X + (size_t)grow * FIN + ac4 * 4);
            As[0][ac4 * 4 + 0][r] = v.x;
            As[0][ac4 * 4 + 1][r] = v.y;
            As[0][ac4 * 4 + 2][r] = v.z;
            As[0][ac4 * 4 + 3][r] = v.w;
        }
#pragma unroll
        for (int j = 0; j < 2; j++) {
            int r = br + j * 8;
            cp_async16(smem_u32(&Bs[0][r][bc4 * 4]),
                       W + (size_t)r * HID + bc4 * 4);
        }
        cp_commit();
        cp_wait0();
    }
    __syncthreads();

    int p = 0;
    for (int k0 = 0; k0 < FIN; k0 += 16) {
        const int kn = k0 + 16;
        const bool more = (kn < FIN);
        float4 a0n, a1n;
        if (more) {
            // prefetch next B via cp.async into buffer p^1
#pragma unroll
            for (int j = 0; j < 2; j++) {
                int r = br + j * 8;
                cp_async16(smem_u32(&Bs[p ^ 1][r][bc4 * 4]),
                           W + (size_t)(kn + r) * HID + bc4 * 4);
            }
            cp_commit();
            // prefetch next A into registers
            int g0 = blockRow + ar;
            int g1 = blockRow + ar + 64;
            a0n = make_float4(0.f, 0.f, 0.f, 0.f);
            a1n = make_float4(0.f, 0.f, 0.f, 0.f);
            if (g0 < NN) a0n = *(const float4*)(X + (size_t)g0 * FIN + kn + ac4 * 4);
            if (g1 < NN) a1n = *(const float4*)(X + (size_t)g1 * FIN + kn + ac4 * 4);
        }
        // compute on buffer p
#pragma unroll
        for (int kk = 0; kk < 16; kk++) {
            float a[8], b[8];
            *(float4*)&a[0] = *(float4*)&As[p][kk][ty * 8];
            *(float4*)&a[4] = *(float4*)&As[p][kk][ty * 8 + 4];
            *(float4*)&b[0] = *(float4*)&Bs[p][kk][tx * 8];
            *(float4*)&b[4] = *(float4*)&Bs[p][kk][tx * 8 + 4];
#pragma unroll
            for (int i = 0; i < 8; i++)
#pragma unroll
                for (int j = 0; j < 8; j++)
                    acc[i][j] += a[i] * b[j];
        }
        if (more) {
            As[p ^ 1][ac4 * 4 + 0][ar] = a0n.x;
            As[p ^ 1][ac4 * 4 + 1][ar] = a0n.y;
            As[p ^ 1][ac4 * 4 + 2][ar] = a0n.z;
            As[p ^ 1][ac4 * 4 + 3][ar] = a0n.w;
            As[p ^ 1][ac4 * 4 + 0][ar + 64] = a1n.x;
            As[p ^ 1][ac4 * 4 + 1][ar + 64] = a1n.y;
            As[p ^ 1][ac4 * 4 + 2][ar + 64] = a1n.z;
            As[p ^ 1][ac4 * 4 + 3][ar + 64] = a1n.w;
            cp_wait0();
        }
        __syncthreads();
        p ^= 1;
    }

    float bi[8];
    *(float4*)&bi[0] = *(const float4*)(B + tx * 8);
    *(float4*)&bi[4] = *(const float4*)(B + tx * 8 + 4);
#pragma unroll
    for (int i = 0; i < 8; i++) {
        int row = blockRow + ty * 8 + i;
        if (row >= NN) continue;
        float4 o0 = make_float4(acc[i][0] + bi[0], acc[i][1] + bi[1],
                                acc[i][2] + bi[2], acc[i][3] + bi[3]);
        float4 o1 = make_float4(acc[i][4] + bi[4], acc[i][5] + bi[5],
                                acc[i][6] + bi[6], acc[i][7] + bi[7]);
        float* hp  = d_h  + (size_t)row * HID + tx * 8;
        float* h0p = d_h0 + (size_t)row * HID + tx * 8;
        *(float4*)(hp)      = o0;
        *(float4*)(hp + 4)  = o1;
        *(float4*)(h0p)     = o0;
        *(float4*)(h0p + 4) = o1;
    }
}

// ---------------- aggregation: s = 0.9*(norm-adj @ h) + 0.1*h0 ----------------
// one warp per node, float4 per lane, 4-way edge unroll (MLP=4)
__global__ __launch_bounds__(256) void k_agg() {
    int i = blockIdx.x * 8 + (threadIdx.x >> 5);
    if (i >= NN) return;
    int lane = threadIdx.x & 31;
    const float4* h4 = (const float4*)d_h;
    float di = d_dinv[i];
    float wself = di * di;
    float4 hi = h4[(size_t)i * 32 + lane];
    float a0x = wself * hi.x, a0y = wself * hi.y;
    float a0z = wself * hi.z, a0w = wself * hi.w;
    float a1x = 0.f, a1y = 0.f, a1z = 0.f, a1w = 0.f;
    float a2x = 0.f, a2y = 0.f, a2z = 0.f, a2w = 0.f;
    float a3x = 0.f, a3y = 0.f, a3z = 0.f, a3w = 0.f;
    int beg = d_rowptr[i], end = d_rowptr[i + 1];
    int e = beg;
    int end4 = beg + ((end - beg) & ~3);
    for (; e < end4; e += 4) {
        int2 p0 = d_epack[e];
        int2 p1 = d_epack[e + 1];
        int2 p2 = d_epack[e + 2];
        int2 p3 = d_epack[e + 3];
        float4 v0 = __ldg(&h4[(size_t)p0.x * 32 + lane]);
        float4 v1 = __ldg(&h4[(size_t)p1.x * 32 + lane]);
        float4 v2 = __ldg(&h4[(size_t)p2.x * 32 + lane]);
        float4 v3 = __ldg(&h4[(size_t)p3.x * 32 + lane]);
        float w0 = __int_as_float(p0.y), w1 = __int_as_float(p1.y);
        float w2 = __int_as_float(p2.y), w3 = __int_as_float(p3.y);
        a0x += w0 * v0.x; a0y += w0 * v0.y; a0z += w0 * v0.z; a0w += w0 * v0.w;
        a1x += w1 * v1.x; a1y += w1 * v1.y; a1z += w1 * v1.z; a1w += w1 * v1.w;
        a2x += w2 * v2.x; a2y += w2 * v2.y; a2z += w2 * v2.z; a2w += w2 * v2.w;
        a3x += w3 * v3.x; a3y += w3 * v3.y; a3z += w3 * v3.z; a3w += w3 * v3.w;
    }
    for (; e < end; e++) {
        int2 p0 = d_epack[e];
        float w0 = __int_as_float(p0.y);
        float4 v0 = __ldg(&h4[(size_t)p0.x * 32 + lane]);
        a1x += w0 * v0.x; a1y += w0 * v0.y; a1z += w0 * v0.z; a1w += w0 * v0.w;
    }
    float4 h0v = ((const float4*)d_h0)[(size_t)i * 32 + lane];
    float4 o;
    o.x = 0.9f * ((a0x + a1x) + (a2x + a3x)) + 0.1f * h0v.x;
    o.y = 0.9f * ((a0y + a1y) + (a2y + a3y)) + 0.1f * h0v.y;
    o.z = 0.9f * ((a0z + a1z) + (a2z + a3z)) + 0.1f * h0v.z;
    o.w = 0.9f * ((a0w + a1w) + (a2w + a3w)) + 0.1f * h0v.w;
    ((float4*)d_s)[(size_t)i * 32 + lane] = o;
}

// ---------------- layer GEMM + identity-map mix + ELU ----------------
// h = elu((1-beta)*s + beta*(s @ W)); double-buffered like k_gemm_in
__global__ __launch_bounds__(256, 2) void k_gemm_layer(const float* __restrict__ W,
                                                       float beta) {
    __shared__ float As[2][16][132];
    __shared__ float Bs[2][16][128];
    const int tid = threadIdx.x;
    const int blockRow = blockIdx.x * 128;
    const int tx = tid & 15, ty = tid >> 4;
    const int ar = tid >> 2, ac4 = tid & 3;
    const int br = tid >> 5, bc4 = tid & 31;

    float acc[8][8];
#pragma unroll
    for (int i = 0; i < 8; i++)
#pragma unroll
        for (int j = 0; j < 8; j++) acc[i][j] = 0.f;

    {
#pragma unroll
        for (int j = 0; j < 2; j++) {
            int r = ar + j * 64;
            int grow = blockRow + r;
            float4 v = make_float4(0.f, 0.f, 0.f, 0.f);
            if (grow < NN)
                v = *(const float4*)(d_s + (size_t)grow * HID + ac4 * 4);
            As[0][ac4 * 4 + 0][r] = v.x;
            As[0][ac4 * 4 + 1][r] = v.y;
            As[0][ac4 * 4 + 2][r] = v.z;
            As[0][ac4 * 4 + 3][r] = v.w;
        }
#pragma unroll
        for (int j = 0; j < 2; j++) {
            int r = br + j * 8;
            cp_async16(smem_u32(&Bs[0][r][bc4 * 4]),
                       W + (size_t)r * HID + bc4 * 4);
        }
        cp_commit();
        cp_wait0();
    }
    __syncthreads();

    int p = 0;
    for (int k0 = 0; k0 < HID; k0 += 16) {
        const int kn = k0 + 16;
        const bool more = (kn < HID);
        float4 a0n, a1n;
        if (more) {
#pragma unroll
            for (int j = 0; j < 2; j++) {
                int r = br + j * 8;
                cp_async16(smem_u32(&Bs[p ^ 1][r][bc4 * 4]),
                           W + (size_t)(kn + r) * HID + bc4 * 4);
            }
            cp_commit();
            int g0 = blockRow + ar;
            int g1 = blockRow + ar + 64;
            a0n = make_float4(0.f, 0.f, 0.f, 0.f);
            a1n = make_float4(0.f, 0.f, 0.f, 0.f);
            if (g0 < NN) a0n = *(const float4*)(d_s + (size_t)g0 * HID + kn + ac4 * 4);
            if (g1 < NN) a1n = *(const float4*)(d_s + (size_t)g1 * HID + kn + ac4 * 4);
        }
#pragma unroll
        for (int kk = 0; kk < 16; kk++) {
            float a[8], b[8];
            *(float4*)&a[0] = *(float4*)&As[p][kk][ty * 8];
            *(float4*)&a[4] = *(float4*)&As[p][kk][ty * 8 + 4];
            *(float4*)&b[0] = *(float4*)&Bs[p][kk][tx * 8];
            *(float4*)&b[4] = *(float4*)&Bs[p][kk][tx * 8 + 4];
#pragma unroll
            for (int i = 0; i < 8; i++)
#pragma unroll
                for (int j = 0; j < 8; j++)
                    acc[i][j] += a[i] * b[j];
        }
        if (more) {
            As[p ^ 1][ac4 * 4 + 0][ar] = a0n.x;
            As[p ^ 1][ac4 * 4 + 1][ar] = a0n.y;
            As[p ^ 1][ac4 * 4 + 2][ar] = a0n.z;
            As[p ^ 1][ac4 * 4 + 3][ar] = a0n.w;
            As[p ^ 1][ac4 * 4 + 0][ar + 64] = a1n.x;
            As[p ^ 1][ac4 * 4 + 1][ar + 64] = a1n.y;
            As[p ^ 1][ac4 * 4 + 2][ar + 64] = a1n.z;
            As[p ^ 1][ac4 * 4 + 3][ar + 64] = a1n.w;
            cp_wait0();
        }
        __syncthreads();
        p ^= 1;
    }

    const float omb = 1.f - beta;
#pragma unroll
    for (int i = 0; i < 8; i++) {
        int row = blockRow + ty * 8 + i;
        if (row >= NN) continue;
        const float* sp = d_s + (size_t)row * HID + tx * 8;
        float4 s0 = *(const float4*)(sp);
        float4 s1 = *(const float4*)(sp + 4);
        float sv[8] = {s0.x, s0.y, s0.z, s0.w, s1.x, s1.y, s1.z, s1.w};
        float ov[8];
#pragma unroll
        for (int j = 0; j < 8; j++) {
            float v = omb * sv[j] + beta * acc[i][j];
            ov[j] = (v > 0.f) ? v : expm1f(v);
        }
        float* hp = d_h + (size_t)row * HID + tx * 8;
        *(float4*)(hp)     = make_float4(ov[0], ov[1], ov[2], ov[3]);
        *(float4*)(hp + 4) = make_float4(ov[4], ov[5], ov[6], ov[7]);
    }
}

// ---------------- output GEMM + log_softmax ----------------
__global__ __launch_bounds__(256) void k_out(const float* __restrict__ Wo,
                                             const float* __restrict__ Bo,
                                             float* __restrict__ out) {
    __shared__ float ws[128][64];   // 32 KB
    __shared__ float hs[32][128];   // 16 KB
    const int tid = threadIdx.x;
    const int base = blockIdx.x * 32;
#pragma unroll
    for (int j = 0; j < 8; j++) {
        int idx = tid + j * 256;
        int r = idx >> 4, c4 = idx & 15;
        *(float4*)&ws[r][c4 * 4] = *(const float4*)(Wo + (size_t)r * NC + c4 * 4);
    }
#pragma unroll
    for (int j = 0; j < 4; j++) {
        int idx = tid + j * 256;
        int r = idx >> 5, c4 = idx & 31;
        *(float4*)&hs[r][c4 * 4] =
            *(const float4*)(d_h + (size_t)(base + r) * HID + c4 * 4);
    }
    __syncthreads();
    const int w = tid >> 5, lane = tid & 31;
    float b0 = Bo[lane], b1 = Bo[lane + 32];
    float acc[4][2];
#pragma unroll
    for (int r = 0; r < 4; r++) { acc[r][0] = 0.f; acc[r][1] = 0.f; }
    for (int k = 0; k < HID; k++) {
        float wv0 = ws[k][lane];
        float wv1 = ws[k][lane + 32];
#pragma unroll
        for (int r = 0; r < 4; r++) {
            float hv = hs[w * 4 + r][k];
            acc[r][0] += hv * wv0;
            acc[r][1] += hv * wv1;
        }
    }
#pragma unroll
    for (int r = 0; r < 4; r++) {
        int row = base + w * 4 + r;
        float v0 = acc[r][0] + b0;
        float v1 = acc[r][1] + b1;
        float m = fmaxf(v0, v1);
#pragma unroll
        for (int off = 16; off; off >>= 1)
            m = fmaxf(m, __shfl_xor_sync(0xffffffff, m, off));
        float ssum = expf(v0 - m) + expf(v1 - m);
#pragma unroll
        for (int off = 16; off; off >>= 1)
            ssum += __shfl_xor_sync(0xffffffff, ssum, off);
        float lse = m + logf(ssum);
        out[(size_t)row * NC + lane]      = v0 - lse;
        out[(size_t)row * NC + lane + 32] = v1 - lse;
    }
}

// ---------------- launch ----------------
extern "C" void kernel_launch(void* const* d_in, const int* in_sizes, int n_in,
                              void* d_out, int out_size) {
    const float* x      = (const float*)d_in[0];
    const void*  ei     = d_in[1];
    const float* w_in   = (const float*)d_in[2];
    const float* b_in   = (const float*)d_in[3];
    const float* conv_w = (const float*)d_in[4];
    const float* w_out  = (const float*)d_in[5];
    const float* b_out  = (const float*)d_in[6];
    float*       out    = (float*)d_out;

    // gemm_in kept as 4th launch so the ncu window profiles it again
    k_init<<<(NN + 255) / 256, 256>>>(ei);
    k_prep_edges<<<(NE + 255) / 256, 256>>>(ei);
    k_scan_dinv<<<1, 1024>>>();
    k_gemm_in<<<(NN + 127) / 128, 256>>>(x, w_in, b_in);
    k_scatter<<<(NE + 255) / 256, 256>>>();

    for (int l = 0; l < NL; l++) {
        float beta = (float)log(0.5 / (double)(l + 1) + 1.0);
        k_agg<<<(NN + 7) / 8, 256>>>();
        k_gemm_layer<<<(NN + 127) / 128, 256>>>(conv_w + (size_t)l * HID * HID, beta);
    }

    k_out<<<NN / 32, 256>>>(w_out, b_out, out);
}